// round 3
// baseline (speedup 1.0000x reference)
#include <cuda_runtime.h>
#include <math.h>

#define T_DIM 2048
#define C_DIM 8
#define S_DIM 16
#define N_DIM 10000
#define NT 128
#define TT 128

// ---------------- scratch ----------------
__device__ float g_H[T_DIM * C_DIM * S_DIM];        // hidden probs [t][c][s]
__device__ float g_cw[T_DIM * C_DIM];               // chain weights [t][c]
__device__ float g_pow[11 * C_DIM * S_DIM * S_DIM]; // A^(2^k) [k][c][i][j]
__device__ float g_H0[C_DIM * S_DIM];
__device__ float g_lse[C_DIM * S_DIM];              // emission row LSE

// ---------------- f32x2 helpers ----------------
typedef unsigned long long u64;
__device__ __forceinline__ u64 pack2(float x, float y) {
    u64 r; asm("mov.b64 %0, {%1,%2};" : "=l"(r) : "f"(x), "f"(y)); return r;
}
__device__ __forceinline__ float2 unpack2(u64 v) {
    float2 r; asm("mov.b64 {%0,%1}, %2;" : "=f"(r.x), "=f"(r.y) : "l"(v)); return r;
}
__device__ __forceinline__ u64 fma2(u64 a, u64 b, u64 c) {
    u64 d; asm("fma.rn.f32x2 %0, %1, %2, %3;" : "=l"(d) : "l"(a), "l"(b), "l"(c)); return d;
}

#define POW_FLOATS (11 * C_DIM * 256)   // 22528 floats = 90112 B

// ---------------- kernel 1: softmax(trans) + matrix powers (in smem) ----------------
__global__ void k_prep_small(const float* __restrict__ init_logits,
                             const float* __restrict__ tr_logits) {
    extern __shared__ float Ps[];
    int tid = threadIdx.x;
    if (tid < 128) {
        const float* row = tr_logits + tid * 16;
        float x[16]; float m = -1e30f;
        #pragma unroll
        for (int j = 0; j < 16; j++) { x[j] = row[j]; m = fmaxf(m, x[j]); }
        float s = 0.f;
        #pragma unroll
        for (int j = 0; j < 16; j++) { x[j] = __expf(x[j] - m); s += x[j]; }
        float inv = 1.0f / s;
        #pragma unroll
        for (int j = 0; j < 16; j++) Ps[tid * 16 + j] = x[j] * inv;
    } else if (tid < 136) {
        int c = tid - 128;
        const float* row = init_logits + c * 16;
        float x[16]; float m = -1e30f;
        #pragma unroll
        for (int j = 0; j < 16; j++) { x[j] = row[j]; m = fmaxf(m, x[j]); }
        float s = 0.f;
        #pragma unroll
        for (int j = 0; j < 16; j++) { x[j] = __expf(x[j] - m); s += x[j]; }
        float inv = 1.0f / s;
        #pragma unroll
        for (int j = 0; j < 16; j++) g_H0[c * 16 + j] = x[j] * inv;
    }
    __syncthreads();
    for (int k = 1; k < 11; k++) {
        for (int e = tid; e < C_DIM * 256; e += 256) {
            int c = e >> 8, ij = e & 255, i = ij >> 4, j = ij & 15;
            const float* P = Ps + (k - 1) * C_DIM * 256 + c * 256;
            float s = 0.f;
            #pragma unroll
            for (int m2 = 0; m2 < 16; m2++) s += P[i * 16 + m2] * P[m2 * 16 + j];
            Ps[k * C_DIM * 256 + c * 256 + ij] = s;
        }
        __syncthreads();
    }
    float4* dst = (float4*)g_pow;
    const float4* src = (const float4*)Ps;
    for (int idx = tid; idx < POW_FLOATS / 4; idx += 256) dst[idx] = src[idx];
}

// ---------------- kernel 2: chain-weight softmax ----------------
__global__ void k_cw(const float* __restrict__ cw_logits) {
    int t = blockIdx.x * blockDim.x + threadIdx.x;
    if (t >= T_DIM) return;
    float x[8]; float m = -1e30f;
    #pragma unroll
    for (int c = 0; c < 8; c++) { x[c] = cw_logits[t * 8 + c]; m = fmaxf(m, x[c]); }
    float s = 0.f;
    #pragma unroll
    for (int c = 0; c < 8; c++) { x[c] = __expf(x[c] - m); s += x[c]; }
    float inv = 1.0f / s;
    #pragma unroll
    for (int c = 0; c < 8; c++) g_cw[t * 8 + c] = x[c] * inv;
}

// ---------------- kernel 3: emission row LSE only ----------------
__global__ void k_lse(const float* __restrict__ em_logits) {
    __shared__ float red[256];
    int row = blockIdx.x;  // (c*16+s)
    int tid = threadIdx.x;
    const float* src = em_logits + (size_t)row * N_DIM;
    float m = -1e30f;
    for (int n = tid; n < N_DIM; n += 256) m = fmaxf(m, src[n]);
    red[tid] = m; __syncthreads();
    for (int o = 128; o; o >>= 1) { if (tid < o) red[tid] = fmaxf(red[tid], red[tid + o]); __syncthreads(); }
    m = red[0]; __syncthreads();
    float s = 0.f;
    for (int n = tid; n < N_DIM; n += 256) s += __expf(src[n] - m);
    red[tid] = s; __syncthreads();
    for (int o = 128; o; o >>= 1) { if (tid < o) red[tid] += red[tid + o]; __syncthreads(); }
    if (tid == 0) g_lse[row] = m + __logf(red[0]);
}

// ---------------- kernel 4: hidden states, warp-coop, 2-task ILP ----------------
// Warp pair: tasks (w + iter*16, w + iter*16 + 8) -> t values (tA, tA+2), same chains.
__global__ void __launch_bounds__(256) k_H(float* __restrict__ out_hidden) {
    extern __shared__ float Ps[];   // staged g_pow
    int tid = threadIdx.x;
    {
        float4* dst = (float4*)Ps;
        const float4* src = (const float4*)g_pow;
        for (int idx = tid; idx < POW_FLOATS / 4; idx += 256) dst[idx] = src[idx];
    }
    __syncthreads();

    int w = tid >> 5;
    int lane = tid & 31;
    int s = lane & 15;
    int t0 = blockIdx.x * 16;
    int c = 2 * (w & 3) + (lane >> 4);
    float h0v = g_H0[c * 16 + s];

    #pragma unroll 1
    for (int iter = 0; iter < 4; iter++) {
        int taskA = w + iter * 16;
        int tA = t0 + (taskA >> 2);
        int tB = tA + 2;

        float hA = h0v, hB = h0v;
        #pragma unroll
        for (int k = 0; k < 11; k++) {
            int bA = (tA >> k) & 1;
            int bB = (tB >> k) & 1;
            if (bA | bB) {
                const float* P = Ps + (k * 8 + c) * 256;
                float pcol[16];
                #pragma unroll
                for (int i = 0; i < 16; i++) pcol[i] = P[i * 16 + s];
                if (bA) {
                    float n0 = 0.f, n1 = 0.f;
                    #pragma unroll
                    for (int i = 0; i < 8; i++) {
                        n0 = fmaf(__shfl_sync(0xffffffffu, hA, 2 * i,     16), pcol[2 * i],     n0);
                        n1 = fmaf(__shfl_sync(0xffffffffu, hA, 2 * i + 1, 16), pcol[2 * i + 1], n1);
                    }
                    hA = n0 + n1;
                }
                if (bB) {
                    float n0 = 0.f, n1 = 0.f;
                    #pragma unroll
                    for (int i = 0; i < 8; i++) {
                        n0 = fmaf(__shfl_sync(0xffffffffu, hB, 2 * i,     16), pcol[2 * i],     n0);
                        n1 = fmaf(__shfl_sync(0xffffffffu, hB, 2 * i + 1, 16), pcol[2 * i + 1], n1);
                    }
                    hB = n0 + n1;
                }
            }
        }
        int idxA = (tA * 8 + c) * 16 + s;
        int idxB = (tB * 8 + c) * 16 + s;
        g_H[idxA] = hA;
        g_H[idxB] = hB;
        if (out_hidden) { out_hidden[idxA] = __logf(hA); out_hidden[idxB] = __logf(hB); }
    }
}

// ---------------- kernel 5: main emission GEMM + log + chain mix ----------------
// 512 threads; tile 128 n x 128 t. H & cw pre-duplicated in smem as (v,v) u64.
// E tile built on the fly: exp(logit - lse).
__global__ void __launch_bounds__(512, 1)
k_main(const float* __restrict__ em_logits,
       float* __restrict__ out_obs, float* __restrict__ out_obs_c) {
    extern __shared__ float smem[];
    float* Es   = smem;                         // 16384 f (64KB)
    u64*   Hs2  = (u64*)(smem + 16384);         // 16384 u64 (128KB)
    u64*   CWs2 = (u64*)(smem + 16384 + 32768); // 1024 u64 (8KB)
    float* LSEs = smem + 16384 + 32768 + 2048;  // 128 f
    int tid = threadIdx.x;
    int n0 = blockIdx.x * NT;
    int t0 = blockIdx.y * TT;

    if (tid < 128) LSEs[tid] = g_lse[tid];
    __syncthreads();

    // E tile: exp(logit - lse), zero-fill OOB n
    float4* Es4 = (float4*)Es;
    for (int idx = tid; idx < 128 * 32; idx += 512) {
        int r = idx >> 5, q = idx & 31;
        int n = n0 + q * 4;
        float4 o = make_float4(0.f, 0.f, 0.f, 0.f);
        if (n < N_DIM) {
            float4 v = *(const float4*)(em_logits + (size_t)r * N_DIM + n);
            float l = LSEs[r];
            o.x = __expf(v.x - l); o.y = __expf(v.y - l);
            o.z = __expf(v.z - l); o.w = __expf(v.w - l);
        }
        Es4[idx] = o;
    }
    // H tile duplicated
    for (int idx = tid; idx < 16384; idx += 512) {
        float v = g_H[t0 * 128 + idx];
        Hs2[idx] = pack2(v, v);
    }
    // cw duplicated
    for (int idx = tid; idx < 1024; idx += 512) {
        float v = g_cw[t0 * 8 + idx];
        CWs2[idx] = pack2(v, v);
    }
    __syncthreads();

    int nq = tid & 31;        // n-quad
    int tg = tid >> 5;        // warp id = t-group (8 t each)
    int tl0 = tg * 8;
    int nvalid = (n0 + nq * 4) < N_DIM;

    u64 wsum[8][2];
    #pragma unroll
    for (int a = 0; a < 8; a++) { wsum[a][0] = 0ULL; wsum[a][1] = 0ULL; }

    const ulonglong2* Es2 = (const ulonglong2*)Es;

    #pragma unroll 1
    for (int c = 0; c < 8; c++) {
        u64 acc[8][2];
        #pragma unroll
        for (int a = 0; a < 8; a++) { acc[a][0] = 0ULL; acc[a][1] = 0ULL; }
        #pragma unroll
        for (int sq = 0; sq < 4; sq++) {
            ulonglong2 ev[4];
            #pragma unroll
            for (int si = 0; si < 4; si++)
                ev[si] = Es2[(c * 16 + sq * 4 + si) * 32 + nq];
            #pragma unroll
            for (int tt = 0; tt < 8; tt++) {
                const u64* hp = Hs2 + (tl0 + tt) * 128 + c * 16 + sq * 4;
                ulonglong2 hva = *(const ulonglong2*)hp;        // s, s+1 dup pairs
                ulonglong2 hvb = *(const ulonglong2*)(hp + 2);  // s+2, s+3
                acc[tt][0] = fma2(hva.x, ev[0].x, acc[tt][0]);
                acc[tt][1] = fma2(hva.x, ev[0].y, acc[tt][1]);
                acc[tt][0] = fma2(hva.y, ev[1].x, acc[tt][0]);
                acc[tt][1] = fma2(hva.y, ev[1].y, acc[tt][1]);
                acc[tt][0] = fma2(hvb.x, ev[2].x, acc[tt][0]);
                acc[tt][1] = fma2(hvb.x, ev[2].y, acc[tt][1]);
                acc[tt][0] = fma2(hvb.y, ev[3].x, acc[tt][0]);
                acc[tt][1] = fma2(hvb.y, ev[3].y, acc[tt][1]);
            }
        }
        #pragma unroll
        for (int tt = 0; tt < 8; tt++) {
            u64 cwp = CWs2[(tl0 + tt) * 8 + c];
            wsum[tt][0] = fma2(cwp, acc[tt][0], wsum[tt][0]);
            wsum[tt][1] = fma2(cwp, acc[tt][1], wsum[tt][1]);
            if (out_obs_c && nvalid) {
                float2 p0 = unpack2(acc[tt][0]);
                float2 p1 = unpack2(acc[tt][1]);
                float4 o = make_float4(__logf(p0.x), __logf(p0.y), __logf(p1.x), __logf(p1.y));
                int t = t0 + tl0 + tt;
                *(float4*)(out_obs_c + (size_t)(t * 8 + c) * N_DIM + n0 + nq * 4) = o;
            }
        }
    }
    #pragma unroll
    for (int tt = 0; tt < 8; tt++) {
        if (nvalid) {
            float2 p0 = unpack2(wsum[tt][0]);
            float2 p1 = unpack2(wsum[tt][1]);
            float4 o = make_float4(__logf(p0.x), __logf(p0.y), __logf(p1.x), __logf(p1.y));
            int t = t0 + tl0 + tt;
            *(float4*)(out_obs + (size_t)t * N_DIM + n0 + nq * 4) = o;
        }
    }
}

// ---------------- launch ----------------
extern "C" void kernel_launch(void* const* d_in, const int* in_sizes, int n_in,
                              void* d_out, int out_size) {
    const float* cw_logits   = (const float*)d_in[0];  // (T, C)
    const float* init_logits = (const float*)d_in[1];  // (C, S)
    const float* em_logits   = (const float*)d_in[2];  // (C, S, N)
    const float* tr_logits   = (const float*)d_in[3];  // (C, S, S)
    float* out = (float*)d_out;

    const long long s0 = (long long)T_DIM * N_DIM;
    const long long s1 = (long long)T_DIM * C_DIM * N_DIM;
    const long long s2 = (long long)T_DIM * C_DIM * S_DIM;
    long long osz = (long long)out_size;

    float* out_obs    = out;
    float* out_obs_c  = (osz >= s0 + s1)      ? out + s0      : nullptr;
    float* out_hidden = (osz >= s0 + s1 + s2) ? out + s0 + s1 : nullptr;

    const int pow_smem  = POW_FLOATS * 4;                        // 90112
    const int main_smem = (16384 + 32768 + 2048 + 128) * 4;      // 205312
    cudaFuncSetAttribute(k_prep_small, cudaFuncAttributeMaxDynamicSharedMemorySize, pow_smem);
    cudaFuncSetAttribute(k_H,          cudaFuncAttributeMaxDynamicSharedMemorySize, pow_smem);
    cudaFuncSetAttribute(k_main,       cudaFuncAttributeMaxDynamicSharedMemorySize, main_smem);

    k_prep_small<<<1, 256, pow_smem>>>(init_logits, tr_logits);
    k_cw<<<8, 256>>>(cw_logits);
    k_lse<<<C_DIM * S_DIM, 256>>>(em_logits);
    k_H<<<T_DIM / 16, 256, pow_smem>>>(out_hidden);

    dim3 grid((N_DIM + NT - 1) / NT, T_DIM / TT);
    k_main<<<grid, 512, main_smem>>>(em_logits, out_obs, out_obs_c);
}

// round 5
// speedup vs baseline: 1.2582x; 1.2582x over previous
#include <cuda_runtime.h>
#include <math.h>

#define T_DIM 2048
#define C_DIM 8
#define S_DIM 16
#define N_DIM 10000
#define NT 64
#define TT 64

// ---------------- scratch ----------------
__device__ float g_E[C_DIM * S_DIM * N_DIM];        // emission probs [c][s][n]
__device__ float g_H[T_DIM * C_DIM * S_DIM];        // hidden probs [t][c][s]
__device__ float g_cw[T_DIM * C_DIM];               // chain weights [t][c]
__device__ float g_pow[11 * C_DIM * S_DIM * S_DIM]; // A^(2^k) [k][c][i][j]
__device__ float g_H0[C_DIM * S_DIM];

// ---------------- f32x2 helpers ----------------
typedef unsigned long long u64;
__device__ __forceinline__ u64 pack2(float x, float y) {
    u64 r; asm("mov.b64 %0, {%1,%2};" : "=l"(r) : "f"(x), "f"(y)); return r;
}
__device__ __forceinline__ float2 unpack2(u64 v) {
    float2 r; asm("mov.b64 {%0,%1}, %2;" : "=f"(r.x), "=f"(r.y) : "l"(v)); return r;
}
__device__ __forceinline__ u64 fma2(u64 a, u64 b, u64 c) {
    u64 d; asm("fma.rn.f32x2 %0, %1, %2, %3;" : "=l"(d) : "l"(a), "l"(b), "l"(c)); return d;
}

#define POW_FLOATS (11 * C_DIM * 256)   // 22528 floats = 90112 B

// ---------------- fused prep: block 0 = trans powers + h0, 1-8 = cw, 9-136 = emis ----------------
__global__ void k_prep(const float* __restrict__ init_logits,
                       const float* __restrict__ tr_logits,
                       const float* __restrict__ cw_logits,
                       const float* __restrict__ em_logits) {
    extern __shared__ float sh[];
    int tid = threadIdx.x;
    int b = blockIdx.x;

    if (b == 0) {
        // ---- transition softmax + repeated squaring (in smem) + h0 ----
        float* Ps = sh;
        if (tid < 128) {
            const float* row = tr_logits + tid * 16;
            float x[16]; float m = -1e30f;
            #pragma unroll
            for (int j = 0; j < 16; j++) { x[j] = row[j]; m = fmaxf(m, x[j]); }
            float s = 0.f;
            #pragma unroll
            for (int j = 0; j < 16; j++) { x[j] = __expf(x[j] - m); s += x[j]; }
            float inv = 1.0f / s;
            #pragma unroll
            for (int j = 0; j < 16; j++) Ps[tid * 16 + j] = x[j] * inv;
        } else if (tid < 136) {
            int c = tid - 128;
            const float* row = init_logits + c * 16;
            float x[16]; float m = -1e30f;
            #pragma unroll
            for (int j = 0; j < 16; j++) { x[j] = row[j]; m = fmaxf(m, x[j]); }
            float s = 0.f;
            #pragma unroll
            for (int j = 0; j < 16; j++) { x[j] = __expf(x[j] - m); s += x[j]; }
            float inv = 1.0f / s;
            #pragma unroll
            for (int j = 0; j < 16; j++) g_H0[c * 16 + j] = x[j] * inv;
        }
        __syncthreads();
        for (int k = 1; k < 11; k++) {
            for (int e = tid; e < C_DIM * 256; e += 256) {
                int c = e >> 8, ij = e & 255, i = ij >> 4, j = ij & 15;
                const float* P = Ps + (k - 1) * C_DIM * 256 + c * 256;
                float s = 0.f;
                #pragma unroll
                for (int m2 = 0; m2 < 16; m2++) s += P[i * 16 + m2] * P[m2 * 16 + j];
                Ps[k * C_DIM * 256 + c * 256 + ij] = s;
            }
            __syncthreads();
        }
        float4* dst = (float4*)g_pow;
        const float4* src = (const float4*)Ps;
        for (int idx = tid; idx < POW_FLOATS / 4; idx += 256) dst[idx] = src[idx];
    } else if (b <= 8) {
        // ---- chain-weight softmax ----
        int t = (b - 1) * 256 + tid;
        float x[8]; float m = -1e30f;
        #pragma unroll
        for (int c = 0; c < 8; c++) { x[c] = cw_logits[t * 8 + c]; m = fmaxf(m, x[c]); }
        float s = 0.f;
        #pragma unroll
        for (int c = 0; c < 8; c++) { x[c] = __expf(x[c] - m); s += x[c]; }
        float inv = 1.0f / s;
        #pragma unroll
        for (int c = 0; c < 8; c++) g_cw[t * 8 + c] = x[c] * inv;
    } else {
        // ---- emission softmax over N, row (c*16+s) ----
        float* red = sh;
        int row = b - 9;
        const float* src = em_logits + (size_t)row * N_DIM;
        float m = -1e30f;
        for (int n = tid; n < N_DIM; n += 256) m = fmaxf(m, src[n]);
        red[tid] = m; __syncthreads();
        for (int o = 128; o; o >>= 1) { if (tid < o) red[tid] = fmaxf(red[tid], red[tid + o]); __syncthreads(); }
        m = red[0]; __syncthreads();
        float s = 0.f;
        for (int n = tid; n < N_DIM; n += 256) s += __expf(src[n] - m);
        red[tid] = s; __syncthreads();
        for (int o = 128; o; o >>= 1) { if (tid < o) red[tid] += red[tid + o]; __syncthreads(); }
        float lse = m + __logf(red[0]);
        float* dst = g_E + (size_t)row * N_DIM;
        for (int n = tid; n < N_DIM; n += 256) dst[n] = __expf(src[n] - lse);
    }
}

// ---------------- k_H: warp-coop binary decomposition, no smem, 512 blocks ----------------
__global__ void __launch_bounds__(256) k_H(float* __restrict__ out_hidden) {
    int tid = threadIdx.x;
    int w = tid >> 5;
    int lane = tid & 31;
    int s = lane & 15;

    int d = blockIdx.x * 8 + w;
    int tA = (d >> 2) * 2;
    int tB = tA + 1;
    int c = 2 * (d & 3) + (lane >> 4);

    float h0v = g_H0[c * 16 + s];
    float hA = h0v, hB = h0v;

    #pragma unroll
    for (int k = 0; k < 11; k++) {
        int bA = (tA >> k) & 1;
        int bB = (tB >> k) & 1;
        if (bA | bB) {
            const float* P = g_pow + (k * 8 + c) * 256;
            float pcol[16];
            #pragma unroll
            for (int i = 0; i < 16; i++) pcol[i] = P[i * 16 + s];
            if (bA) {
                float n0 = 0.f, n1 = 0.f;
                #pragma unroll
                for (int i = 0; i < 8; i++) {
                    n0 = fmaf(__shfl_sync(0xffffffffu, hA, 2 * i,     16), pcol[2 * i],     n0);
                    n1 = fmaf(__shfl_sync(0xffffffffu, hA, 2 * i + 1, 16), pcol[2 * i + 1], n1);
                }
                hA = n0 + n1;
            }
            if (bB) {
                float n0 = 0.f, n1 = 0.f;
                #pragma unroll
                for (int i = 0; i < 8; i++) {
                    n0 = fmaf(__shfl_sync(0xffffffffu, hB, 2 * i,     16), pcol[2 * i],     n0);
                    n1 = fmaf(__shfl_sync(0xffffffffu, hB, 2 * i + 1, 16), pcol[2 * i + 1], n1);
                }
                hB = n0 + n1;
            }
        }
    }
    int idxA = (tA * 8 + c) * 16 + s;
    int idxB = (tB * 8 + c) * 16 + s;
    g_H[idxA] = hA;
    g_H[idxB] = hB;
    if (out_hidden) { out_hidden[idxA] = __logf(hA); out_hidden[idxB] = __logf(hB); }
}

// ---------------- k_main: tile 64n x 64t, 256 thr, 3 blocks/SM ----------------
// nq = tid&15 (n-quad of 4), tg = tid>>4 (16 groups x 4 t).
__global__ void __launch_bounds__(256, 3)
k_main(float* __restrict__ out_obs, float* __restrict__ out_obs_c) {
    extern __shared__ float smem[];
    float* Es  = smem;                  // [128 rows][64 n] = 8192 f (32KB)
    float* Hs  = smem + 8192;           // [64 t][128]      = 8192 f (32KB)
    float* CWs = smem + 16384;          // [64 t][8 c]      = 512 f (2KB)
    int tid = threadIdx.x;
    int n0 = blockIdx.x * NT;
    int t0 = blockIdx.y * TT;

    // E tile (zero-fill OOB n): 128 rows x 64 n
    float4* Es4 = (float4*)Es;
    for (int idx = tid; idx < 128 * 16; idx += 256) {
        int r = idx >> 4, q = idx & 15;
        int n = n0 + q * 4;
        float4 v;
        if (n < N_DIM) v = *(const float4*)(g_E + (size_t)r * N_DIM + n);
        else v = make_float4(0.f, 0.f, 0.f, 0.f);
        Es4[idx] = v;
    }
    // H tile
    {
        const float4* src = (const float4*)(g_H + t0 * 128);
        float4* dst = (float4*)Hs;
        for (int idx = tid; idx < 2048; idx += 256) dst[idx] = src[idx];
    }
    for (int idx = tid; idx < 512; idx += 256) CWs[idx] = g_cw[t0 * 8 + idx];
    __syncthreads();

    int nq = tid & 15;
    int tg = tid >> 4;
    int tl0 = tg * 4;
    int nvalid = (n0 + nq * 4) < N_DIM;

    u64 wsum[4][2];
    #pragma unroll
    for (int a = 0; a < 4; a++) { wsum[a][0] = 0ULL; wsum[a][1] = 0ULL; }

    const ulonglong2* Es2 = (const ulonglong2*)Es;  // row = 64 floats = 16 ulonglong2

    #pragma unroll 1
    for (int c = 0; c < 8; c++) {
        u64 acc[4][2];
        #pragma unroll
        for (int a = 0; a < 4; a++) { acc[a][0] = 0ULL; acc[a][1] = 0ULL; }
        #pragma unroll
        for (int sq = 0; sq < 4; sq++) {
            ulonglong2 ev[4];
            #pragma unroll
            for (int si = 0; si < 4; si++)
                ev[si] = Es2[(c * 16 + sq * 4 + si) * 16 + nq];   // stride 16 (fixed)
            #pragma unroll
            for (int tt = 0; tt < 4; tt++) {
                float4 hv = *(const float4*)(Hs + (tl0 + tt) * 128 + c * 16 + sq * 4);
                #pragma unroll
                for (int si = 0; si < 4; si++) {
                    float hsc = ((const float*)&hv)[si];
                    u64 hh = pack2(hsc, hsc);
                    acc[tt][0] = fma2(hh, ev[si].x, acc[tt][0]);
                    acc[tt][1] = fma2(hh, ev[si].y, acc[tt][1]);
                }
            }
        }
        #pragma unroll
        for (int tt = 0; tt < 4; tt++) {
            float cw = CWs[(tl0 + tt) * 8 + c];
            u64 cwp = pack2(cw, cw);
            wsum[tt][0] = fma2(cwp, acc[tt][0], wsum[tt][0]);
            wsum[tt][1] = fma2(cwp, acc[tt][1], wsum[tt][1]);
            if (out_obs_c && nvalid) {
                float2 p0 = unpack2(acc[tt][0]);
                float2 p1 = unpack2(acc[tt][1]);
                float4 o = make_float4(__logf(p0.x), __logf(p0.y), __logf(p1.x), __logf(p1.y));
                int t = t0 + tl0 + tt;
                *(float4*)(out_obs_c + (size_t)(t * 8 + c) * N_DIM + n0 + nq * 4) = o;
            }
        }
    }
    #pragma unroll
    for (int tt = 0; tt < 4; tt++) {
        if (nvalid) {
            float2 p0 = unpack2(wsum[tt][0]);
            float2 p1 = unpack2(wsum[tt][1]);
            float4 o = make_float4(__logf(p0.x), __logf(p0.y), __logf(p1.x), __logf(p1.y));
            int t = t0 + tl0 + tt;
            *(float4*)(out_obs + (size_t)t * N_DIM + n0 + nq * 4) = o;
        }
    }
}

// ---------------- launch ----------------
extern "C" void kernel_launch(void* const* d_in, const int* in_sizes, int n_in,
                              void* d_out, int out_size) {
    const float* cw_logits   = (const float*)d_in[0];  // (T, C)
    const float* init_logits = (const float*)d_in[1];  // (C, S)
    const float* em_logits   = (const float*)d_in[2];  // (C, S, N)
    const float* tr_logits   = (const float*)d_in[3];  // (C, S, S)
    float* out = (float*)d_out;

    const long long s0 = (long long)T_DIM * N_DIM;
    const long long s1 = (long long)T_DIM * C_DIM * N_DIM;
    const long long s2 = (long long)T_DIM * C_DIM * S_DIM;
    long long osz = (long long)out_size;

    float* out_obs    = out;
    float* out_obs_c  = (osz >= s0 + s1)      ? out + s0      : nullptr;
    float* out_hidden = (osz >= s0 + s1 + s2) ? out + s0 + s1 : nullptr;

    const int prep_smem = POW_FLOATS * 4;            // 90112
    const int main_smem = (8192 + 8192 + 512) * 4;   // 67584
    cudaFuncSetAttribute(k_prep, cudaFuncAttributeMaxDynamicSharedMemorySize, prep_smem);
    cudaFuncSetAttribute(k_main, cudaFuncAttributeMaxDynamicSharedMemorySize, main_smem);

    k_prep<<<9 + C_DIM * S_DIM, 256, prep_smem>>>(init_logits, tr_logits, cw_logits, em_logits);
    k_H<<<512, 256>>>(out_hidden);

    dim3 grid((N_DIM + NT - 1) / NT, T_DIM / TT);
    k_main<<<grid, 256, main_smem>>>(out_obs, out_obs_c);
}